// round 1
// baseline (speedup 1.0000x reference)
#include <cuda_runtime.h>
#include <cuda_bf16.h>
#include <math.h>

// Problem constants (fixed shapes from setup_inputs)
#define BB 4
#define TT 1024
#define SS 1024
#define DD 1024
#define HH 16
#define HSZ 64
#define DFF 4096
#define ROWS (BB*TT)       // 4096

// ---------------- scratch buffers (static device allocations) ----------------
__device__ float buf_xn[ROWS * DD];        // 16 MB  rmsnorm output / residual
__device__ float buf_q [ROWS * 2*DD];      // 32 MB  q projections (H*2*hs = 2048)
__device__ float buf_k [ROWS * 2*DD];      // 32 MB
__device__ float buf_v [ROWS * DD];        // 16 MB
__device__ float buf_o [ROWS * DD];        // 16 MB  attention output (pre-Wo)
__device__ float buf_h [ROWS * DD];        // 16 MB  hidden state
__device__ float buf_f1[ROWS * DFF];       // 64 MB
__device__ float buf_f2[ROWS * DFF];       // 64 MB

// ---------------- RMSNorm: one block per row ----------------
__global__ void rmsnorm_kernel(const float* __restrict__ x,
                               const float* __restrict__ g,
                               float* __restrict__ out)
{
    int row = blockIdx.x;
    const float* xr = x + (size_t)row * DD;
    float* orow = out + (size_t)row * DD;

    float s = 0.f;
    for (int i = threadIdx.x * 4; i < DD; i += blockDim.x * 4) {
        float4 v = *(const float4*)(xr + i);
        s += v.x*v.x + v.y*v.y + v.z*v.z + v.w*v.w;
    }
    __shared__ float red[256];
    red[threadIdx.x] = s;
    __syncthreads();
    for (int st = 128; st > 0; st >>= 1) {
        if (threadIdx.x < st) red[threadIdx.x] += red[threadIdx.x + st];
        __syncthreads();
    }
    float inv = rsqrtf(red[0] * (1.f / DD) + 1e-6f);

    for (int i = threadIdx.x * 4; i < DD; i += blockDim.x * 4) {
        float4 v = *(const float4*)(xr + i);
        float4 gv = *(const float4*)(g + i);
        float4 r;
        r.x = v.x * inv * gv.x;
        r.y = v.y * inv * gv.y;
        r.z = v.z * inv * gv.z;
        r.w = v.w * inv * gv.w;
        *(float4*)(orow + i) = r;
    }
}

// ---------------- SGEMM: C = scale*(A@B) [+ add], 128x128x16 tiles ----------------
// A: [M,K] row-major, B: [K,N] row-major. M%128==0, N%128==0, K%16==0.
__global__ __launch_bounds__(256)
void gemm_kernel(const float* __restrict__ A, const float* __restrict__ Bmat,
                 const float* __restrict__ add, float* __restrict__ C,
                 int M, int N, int K, float scale)
{
    const int BM = 128, BN = 128, BK = 16;
    __shared__ float As[BK][BM];
    __shared__ float Bs[BK][BN];

    int tid = threadIdx.x;
    int tx = tid & 15;   // n-direction
    int ty = tid >> 4;   // m-direction
    int m0 = blockIdx.y * BM;
    int n0 = blockIdx.x * BN;

    float acc[8][8];
    #pragma unroll
    for (int i = 0; i < 8; i++)
        #pragma unroll
        for (int j = 0; j < 8; j++) acc[i][j] = 0.f;

    for (int k0 = 0; k0 < K; k0 += BK) {
        // load A tile (128x16) transposed into As[k][m]
        #pragma unroll
        for (int i = 0; i < 2; i++) {
            int idx = tid * 2 + i;            // 0..511 float4s
            int r = idx >> 2;                 // 0..127
            int c = (idx & 3) * 4;            // 0,4,8,12
            float4 va = *(const float4*)(A + (size_t)(m0 + r) * K + k0 + c);
            As[c + 0][r] = va.x;
            As[c + 1][r] = va.y;
            As[c + 2][r] = va.z;
            As[c + 3][r] = va.w;
        }
        // load B tile (16x128)
        #pragma unroll
        for (int i = 0; i < 2; i++) {
            int idx = tid * 2 + i;
            int r = idx >> 5;                 // 0..15
            int c = (idx & 31) * 4;           // 0..124
            *(float4*)(&Bs[r][c]) = *(const float4*)(Bmat + (size_t)(k0 + r) * N + n0 + c);
        }
        __syncthreads();

        #pragma unroll
        for (int k = 0; k < BK; k++) {
            float ra[8], rb[8];
            #pragma unroll
            for (int i = 0; i < 8; i++) ra[i] = As[k][ty * 8 + i];
            #pragma unroll
            for (int j = 0; j < 8; j++) rb[j] = Bs[k][tx * 8 + j];
            #pragma unroll
            for (int i = 0; i < 8; i++)
                #pragma unroll
                for (int j = 0; j < 8; j++)
                    acc[i][j] += ra[i] * rb[j];
        }
        __syncthreads();
    }

    // epilogue
    #pragma unroll
    for (int i = 0; i < 8; i++) {
        size_t row = (size_t)(m0 + ty * 8 + i);
        #pragma unroll
        for (int j = 0; j < 8; j += 4) {
            size_t idx = row * N + n0 + tx * 8 + j;
            float4 r;
            r.x = acc[i][j + 0] * scale;
            r.y = acc[i][j + 1] * scale;
            r.z = acc[i][j + 2] * scale;
            r.w = acc[i][j + 3] * scale;
            if (add) {
                float4 a = *(const float4*)(add + idx);
                r.x += a.x; r.y += a.y; r.z += a.z; r.w += a.w;
            }
            *(float4*)(C + idx) = r;
        }
    }
}

// ---------------- Differential attention: one block per (t, h, b) ----------------
// q: [B,T,H*2*64], k: [B,S,H*2*64], v: [B,S,H*64], o: [B,T,H*64]
// Fuses: dual softmax, lambda combine, AV, per-head RMSNorm * (1-lambda_init)
__global__ __launch_bounds__(256)
void diff_attn_kernel(const float* __restrict__ q, const float* __restrict__ k,
                      const float* __restrict__ v,
                      const float* __restrict__ lq1, const float* __restrict__ lk1,
                      const float* __restrict__ lq2, const float* __restrict__ lk2,
                      float* __restrict__ o, int causal)
{
    int t = blockIdx.x, h = blockIdx.y, b = blockIdx.z;
    int tid = threadIdx.x;

    __shared__ float q1s[64], q2s[64];
    __shared__ float arr1[SS], arr2[SS];
    __shared__ float red1[256], red2[256];
    __shared__ float part[4][64];
    __shared__ float lam_s;

    const float* qrow = q + ((size_t)((b * TT + t) * HH + h)) * 128;
    if (tid < 64) q1s[tid] = qrow[tid];
    else if (tid < 128) q2s[tid - 64] = qrow[tid];

    if (tid == 0) {
        float s1 = 0.f, s2 = 0.f;
        for (int d = 0; d < 64; d++) {
            s1 += lq1[h * 64 + d] * lk1[h * 64 + d];
            s2 += lq2[h * 64 + d] * lk2[h * 64 + d];
        }
        lam_s = expf(s1) - expf(s2) + 0.8f;
    }
    __syncthreads();

    int Send = causal ? (t + 1) : SS;
    const float scale = 0.125f;   // 1/sqrt(64)

    // phase 1: scores + running max
    float m1 = -1e30f, m2 = -1e30f;
    for (int s = tid; s < Send; s += 256) {
        const float* krow = k + ((size_t)((b * SS + s) * HH + h)) * 128;
        float d1 = 0.f, d2 = 0.f;
        #pragma unroll
        for (int d = 0; d < 64; d += 4) {
            float4 k1v = *(const float4*)(krow + d);
            float4 k2v = *(const float4*)(krow + 64 + d);
            d1 += q1s[d] * k1v.x + q1s[d + 1] * k1v.y + q1s[d + 2] * k1v.z + q1s[d + 3] * k1v.w;
            d2 += q2s[d] * k2v.x + q2s[d + 1] * k2v.y + q2s[d + 2] * k2v.z + q2s[d + 3] * k2v.w;
        }
        d1 *= scale; d2 *= scale;
        arr1[s] = d1; arr2[s] = d2;
        m1 = fmaxf(m1, d1); m2 = fmaxf(m2, d2);
    }
    red1[tid] = m1; red2[tid] = m2;
    __syncthreads();
    for (int st = 128; st > 0; st >>= 1) {
        if (tid < st) {
            red1[tid] = fmaxf(red1[tid], red1[tid + st]);
            red2[tid] = fmaxf(red2[tid], red2[tid + st]);
        }
        __syncthreads();
    }
    float M1 = red1[0], M2 = red2[0];
    __syncthreads();

    // phase 2: exp + sums
    float s1 = 0.f, s2 = 0.f;
    for (int s = tid; s < Send; s += 256) {
        float e1 = expf(arr1[s] - M1);
        float e2 = expf(arr2[s] - M2);
        arr1[s] = e1; arr2[s] = e2;
        s1 += e1; s2 += e2;
    }
    red1[tid] = s1; red2[tid] = s2;
    __syncthreads();
    for (int st = 128; st > 0; st >>= 1) {
        if (tid < st) { red1[tid] += red1[tid + st]; red2[tid] += red2[tid + st]; }
        __syncthreads();
    }
    float inv1 = 1.f / red1[0];
    float inv2 = lam_s / red2[0];
    __syncthreads();

    // phase 3: combined weights
    for (int s = tid; s < Send; s += 256)
        arr1[s] = arr1[s] * inv1 - arr2[s] * inv2;
    __syncthreads();

    // phase 4: o[d] = sum_s attn[s] * v[s][d]
    int d = tid & 63, g = tid >> 6;
    float acc = 0.f;
    for (int s = g; s < Send; s += 4)
        acc += arr1[s] * v[((size_t)((b * SS + s) * HH + h)) * 64 + d];
    part[g][d] = acc;
    __syncthreads();

    float ov = 0.f;
    if (tid < 64) {
        ov = part[0][tid] + part[1][tid] + part[2][tid] + part[3][tid];
        red1[tid] = ov * ov;
    }
    __syncthreads();
    if (tid < 32) red1[tid] += red1[tid + 32]; __syncthreads();
    if (tid < 16) red1[tid] += red1[tid + 16]; __syncthreads();
    if (tid < 8)  red1[tid] += red1[tid + 8];  __syncthreads();
    if (tid < 4)  red1[tid] += red1[tid + 4];  __syncthreads();
    if (tid < 2)  red1[tid] += red1[tid + 2];  __syncthreads();
    if (tid < 1)  red1[tid] += red1[tid + 1];  __syncthreads();

    if (tid < 64) {
        float on = ov * rsqrtf(red1[0] * (1.f / 64.f) + 1e-6f) * 0.2f;
        o[((size_t)((b * TT + t) * HH + h)) * 64 + tid] = on;
    }
}

// ---------------- SwiGLU elementwise: a = silu(a) * b ----------------
__global__ void swiglu_ew_kernel(float* __restrict__ a, const float* __restrict__ b, int n)
{
    int i = blockIdx.x * blockDim.x + threadIdx.x;
    if (i < n) {
        float x = a[i];
        a[i] = (x / (1.f + expf(-x))) * b[i];
    }
}

// ---------------- launch ----------------
static inline void gemm(const float* A, const float* B, const float* add,
                        float* C, int M, int N, int K, float scale)
{
    dim3 grid(N / 128, M / 128);
    gemm_kernel<<<grid, 256>>>(A, B, add, C, M, N, K, scale);
}

extern "C" void kernel_launch(void* const* d_in, const int* in_sizes, int n_in,
                              void* d_out, int out_size)
{
    const float* x     = (const float*)d_in[0];
    const float* enc   = (const float*)d_in[1];
    const float* Wq_s  = (const float*)d_in[2];
    const float* Wk_s  = (const float*)d_in[3];
    const float* Wv_s  = (const float*)d_in[4];
    const float* Wo_s  = (const float*)d_in[5];
    const float* lq1_s = (const float*)d_in[6];
    const float* lk1_s = (const float*)d_in[7];
    const float* lq2_s = (const float*)d_in[8];
    const float* lk2_s = (const float*)d_in[9];
    const float* Wq_c  = (const float*)d_in[10];
    const float* Wk_c  = (const float*)d_in[11];
    const float* Wv_c  = (const float*)d_in[12];
    const float* Wo_c  = (const float*)d_in[13];
    const float* lq1_c = (const float*)d_in[14];
    const float* lk1_c = (const float*)d_in[15];
    const float* lq2_c = (const float*)d_in[16];
    const float* lk2_c = (const float*)d_in[17];
    const float* g_rms = (const float*)d_in[18];
    const float* W1    = (const float*)d_in[19];
    const float* W2    = (const float*)d_in[20];
    const float* W3    = (const float*)d_in[21];
    float* out = (float*)d_out;

    float *xn, *qb, *kb, *vb, *ob, *hb, *f1, *f2;
    cudaGetSymbolAddress((void**)&xn, buf_xn);
    cudaGetSymbolAddress((void**)&qb, buf_q);
    cudaGetSymbolAddress((void**)&kb, buf_k);
    cudaGetSymbolAddress((void**)&vb, buf_v);
    cudaGetSymbolAddress((void**)&ob, buf_o);
    cudaGetSymbolAddress((void**)&hb, buf_h);
    cudaGetSymbolAddress((void**)&f1, buf_f1);
    cudaGetSymbolAddress((void**)&f2, buf_f2);

    const int M = ROWS;
    dim3 attn_grid(TT, HH, BB);

    // 1) xn = rmsnorm(x, g_rms)
    rmsnorm_kernel<<<ROWS, 256>>>(x, g_rms, xn);

    // 2) self-attention projections
    gemm(xn, Wq_s, nullptr, qb, M, 2 * DD, DD, 1.f);
    gemm(xn, Wk_s, nullptr, kb, M, 2 * DD, DD, 1.f);
    gemm(xn, Wv_s, nullptr, vb, M, DD, DD, 1.f);

    // 3) causal diff attention
    diff_attn_kernel<<<attn_grid, 256>>>(qb, kb, vb, lq1_s, lk1_s, lq2_s, lk2_s, ob, 1);

    // 4) h = o @ Wo_s + xn   (residual)
    gemm(ob, Wo_s, xn, hb, M, DD, DD, 1.f);

    // 5) cross-attention projections: q from h, k/v from encoder_output
    gemm(hb, Wq_c, nullptr, qb, M, 2 * DD, DD, 1.f);
    gemm(enc, Wk_c, nullptr, kb, M, 2 * DD, DD, 1.f);
    gemm(enc, Wv_c, nullptr, vb, M, DD, DD, 1.f);

    // 6) non-causal diff attention
    diff_attn_kernel<<<attn_grid, 256>>>(qb, kb, vb, lq1_c, lk1_c, lq2_c, lk2_c, ob, 0);

    // 7) h = 2 * (o @ Wo_c)   (h = cross; h = h + h)
    gemm(ob, Wo_c, nullptr, hb, M, DD, DD, 2.f);

    // 8) xn = rmsnorm(h, g_rms)
    rmsnorm_kernel<<<ROWS, 256>>>(hb, g_rms, xn);

    // 9) SwiGLU MLP
    gemm(xn, W1, nullptr, f1, M, DFF, DD, 1.f);
    gemm(xn, W2, nullptr, f2, M, DFF, DD, 1.f);
    {
        int n = ROWS * DFF;
        swiglu_ew_kernel<<<(n + 255) / 256, 256>>>(f1, f2, n);
    }

    // 10) out = f1 @ W3 + h
    gemm(f1, W3, hb, out, M, DD, DFF, 1.f);
}

// round 3
// speedup vs baseline: 5.4225x; 5.4225x over previous
#include <cuda_runtime.h>
#include <cuda_bf16.h>
#include <math.h>

// Problem constants (fixed shapes from setup_inputs)
#define BB 4
#define TT 1024
#define SS 1024
#define DD 1024
#define HH 16
#define HSZ 64
#define DFF 4096
#define ROWS (BB*TT)       // 4096

// ---------------- scratch buffers (static device allocations) ----------------
__device__ float buf_xn[ROWS * DD];        // 16 MB  rmsnorm output / residual
__device__ float buf_q [ROWS * 2*DD];      // 32 MB  q projections (H*2*hs = 2048)
__device__ float buf_k [ROWS * 2*DD];      // 32 MB
__device__ float buf_v [ROWS * DD];        // 16 MB
__device__ float buf_o [ROWS * DD];        // 16 MB  attention output (pre-Wo)
__device__ float buf_h [ROWS * DD];        // 16 MB  hidden state
__device__ float buf_f1[ROWS * DFF];       // 64 MB
__device__ float buf_f2[ROWS * DFF];       // 64 MB

// ---------------- RMSNorm: one block per row ----------------
__global__ void rmsnorm_kernel(const float* __restrict__ x,
                               const float* __restrict__ g,
                               float* __restrict__ out)
{
    int row = blockIdx.x;
    const float* xr = x + (size_t)row * DD;
    float* orow = out + (size_t)row * DD;

    float s = 0.f;
    for (int i = threadIdx.x * 4; i < DD; i += blockDim.x * 4) {
        float4 v = *(const float4*)(xr + i);
        s += v.x*v.x + v.y*v.y + v.z*v.z + v.w*v.w;
    }
    __shared__ float red[256];
    red[threadIdx.x] = s;
    __syncthreads();
    for (int st = 128; st > 0; st >>= 1) {
        if (threadIdx.x < st) red[threadIdx.x] += red[threadIdx.x + st];
        __syncthreads();
    }
    float inv = rsqrtf(red[0] * (1.f / DD) + 1e-6f);

    for (int i = threadIdx.x * 4; i < DD; i += blockDim.x * 4) {
        float4 v = *(const float4*)(xr + i);
        float4 gv = *(const float4*)(g + i);
        float4 r;
        r.x = v.x * inv * gv.x;
        r.y = v.y * inv * gv.y;
        r.z = v.z * inv * gv.z;
        r.w = v.w * inv * gv.w;
        *(float4*)(orow + i) = r;
    }
}

// ---------------- SGEMM: C = scale*(A@B) [+ add], 128x128x16 tiles ----------------
__global__ __launch_bounds__(256, 2)
void gemm_kernel(const float* __restrict__ A, const float* __restrict__ Bmat,
                 const float* __restrict__ add, float* __restrict__ C,
                 int M, int N, int K, float scale)
{
    const int BM = 128, BN = 128, BK = 16;
    __shared__ float As[BK][BM];
    __shared__ float Bs[BK][BN];

    int tid = threadIdx.x;
    int tx = tid & 15;   // n-direction
    int ty = tid >> 4;   // m-direction
    int m0 = blockIdx.y * BM;
    int n0 = blockIdx.x * BN;

    float acc[8][8];
    #pragma unroll
    for (int i = 0; i < 8; i++)
        #pragma unroll
        for (int j = 0; j < 8; j++) acc[i][j] = 0.f;

    for (int k0 = 0; k0 < K; k0 += BK) {
        #pragma unroll
        for (int i = 0; i < 2; i++) {
            int idx = tid * 2 + i;            // 0..511 float4s
            int r = idx >> 2;                 // 0..127
            int c = (idx & 3) * 4;            // 0,4,8,12
            float4 va = *(const float4*)(A + (size_t)(m0 + r) * K + k0 + c);
            As[c + 0][r] = va.x;
            As[c + 1][r] = va.y;
            As[c + 2][r] = va.z;
            As[c + 3][r] = va.w;
        }
        #pragma unroll
        for (int i = 0; i < 2; i++) {
            int idx = tid * 2 + i;
            int r = idx >> 5;                 // 0..15
            int c = (idx & 31) * 4;           // 0..124
            *(float4*)(&Bs[r][c]) = *(const float4*)(Bmat + (size_t)(k0 + r) * N + n0 + c);
        }
        __syncthreads();

        #pragma unroll
        for (int k = 0; k < BK; k++) {
            float ra[8], rb[8];
            #pragma unroll
            for (int i = 0; i < 8; i++) ra[i] = As[k][ty * 8 + i];
            #pragma unroll
            for (int j = 0; j < 8; j++) rb[j] = Bs[k][tx * 8 + j];
            #pragma unroll
            for (int i = 0; i < 8; i++)
                #pragma unroll
                for (int j = 0; j < 8; j++)
                    acc[i][j] += ra[i] * rb[j];
        }
        __syncthreads();
    }

    #pragma unroll
    for (int i = 0; i < 8; i++) {
        size_t row = (size_t)(m0 + ty * 8 + i);
        #pragma unroll
        for (int j = 0; j < 8; j += 4) {
            size_t idx = row * N + n0 + tx * 8 + j;
            float4 r;
            r.x = acc[i][j + 0] * scale;
            r.y = acc[i][j + 1] * scale;
            r.z = acc[i][j + 2] * scale;
            r.w = acc[i][j + 3] * scale;
            if (add) {
                float4 a = *(const float4*)(add + idx);
                r.x += a.x; r.y += a.y; r.z += a.z; r.w += a.w;
            }
            *(float4*)(C + idx) = r;
        }
    }
}

// ---------------- Flash-tiled differential attention ----------------
// Block = (q-tile of 64 rows, head, batch). 256 threads, 16x16 layout.
// Thread (ty,tx): q rows ty*4..ty*4+3; s columns INTERLEAVED tx+16*j
// (lane stride 68 floats == 4 mod 32 banks -> conflict-free K reads).
// Dual online softmax, lambda-combine + per-head RMSNorm fused in epilogue.
// q: [B,T,H,2,64]  k: [B,S,H,2,64]  v: [B,S,H,64]  o: [B,T,H,64]
#define APAD 4
#define ALD (64 + APAD)   // 68 floats per row

__global__ __launch_bounds__(256)
void flash_diff_attn_kernel(const float* __restrict__ q, const float* __restrict__ k,
                            const float* __restrict__ v,
                            const float* __restrict__ lq1, const float* __restrict__ lk1,
                            const float* __restrict__ lq2, const float* __restrict__ lk2,
                            float* __restrict__ o, int causal)
{
    extern __shared__ float smem[];
    float (*Q1s)[ALD] = (float(*)[ALD])(smem);
    float (*Q2s)[ALD] = (float(*)[ALD])(smem + 64*ALD);
    float (*K1s)[ALD] = (float(*)[ALD])(smem + 2*64*ALD);
    float (*K2s)[ALD] = (float(*)[ALD])(smem + 3*64*ALD);
    float (*Vs )[ALD] = (float(*)[ALD])(smem + 4*64*ALD);
    float (*P1s)[ALD] = (float(*)[ALD])(smem + 5*64*ALD);
    float (*P2s)[ALD] = (float(*)[ALD])(smem + 6*64*ALD);
    __shared__ float lam_sh;

    int qt = blockIdx.x, h = blockIdx.y, b = blockIdx.z;
    int t0 = qt * 64;
    int tid = threadIdx.x;
    int tx = tid & 15;       // col group (s or d)
    int ty = tid >> 4;       // row group (q)

    // lambda for this head
    if (tid == 0) {
        float s1 = 0.f, s2 = 0.f;
        #pragma unroll 8
        for (int d = 0; d < 64; d++) {
            s1 += lq1[h * 64 + d] * lk1[h * 64 + d];
            s2 += lq2[h * 64 + d] * lk2[h * 64 + d];
        }
        lam_sh = expf(s1) - expf(s2) + 0.8f;
    }

    // load Q tile (both halves), natural [q][d] layout, coalesced float4
    for (int i = tid; i < 64 * 16; i += 256) {
        int r = i >> 4, dg = (i & 15) * 4;
        const float* qrow = q + ((size_t)((b * TT + t0 + r) * HH + h)) * 128;
        *(float4*)&Q1s[r][dg] = *(const float4*)(qrow + dg);
        *(float4*)&Q2s[r][dg] = *(const float4*)(qrow + 64 + dg);
    }

    // per-thread state (replicated across tx within a row)
    float m1[4], m2[4], l1[4], l2[4];
    float o1[4][4], o2[4][4];
    #pragma unroll
    for (int i = 0; i < 4; i++) {
        m1[i] = -1e30f; m2[i] = -1e30f; l1[i] = 0.f; l2[i] = 0.f;
        #pragma unroll
        for (int j = 0; j < 4; j++) { o1[i][j] = 0.f; o2[i][j] = 0.f; }
    }

    int nChunk = causal ? (qt + 1) : (SS / 64);

    for (int ch = 0; ch < nChunk; ch++) {
        int c0 = ch * 64;
        // load K1,K2,V chunk
        for (int i = tid; i < 64 * 16; i += 256) {
            int r = i >> 4, dg = (i & 15) * 4;
            const float* krow = k + ((size_t)((b * SS + c0 + r) * HH + h)) * 128;
            *(float4*)&K1s[r][dg] = *(const float4*)(krow + dg);
            *(float4*)&K2s[r][dg] = *(const float4*)(krow + 64 + dg);
            const float* vrow = v + ((size_t)((b * SS + c0 + r) * HH + h)) * 64;
            *(float4*)&Vs[r][dg] = *(const float4*)(vrow + dg);
        }
        __syncthreads();

        bool diag = causal && (ch == nChunk - 1);

        // ---- scores 1: S1 = Q1 @ K1^T (s column j -> smem row tx + 16*j) ----
        float sc1[4][4];
        #pragma unroll
        for (int i = 0; i < 4; i++)
            #pragma unroll
            for (int j = 0; j < 4; j++) sc1[i][j] = 0.f;
        #pragma unroll
        for (int kk = 0; kk < 64; kk += 4) {
            float4 qa[4], kb[4];
            #pragma unroll
            for (int i = 0; i < 4; i++) qa[i] = *(float4*)&Q1s[ty*4 + i][kk];
            #pragma unroll
            for (int j = 0; j < 4; j++) kb[j] = *(float4*)&K1s[tx + 16*j][kk];
            #pragma unroll
            for (int i = 0; i < 4; i++)
                #pragma unroll
                for (int j = 0; j < 4; j++)
                    sc1[i][j] += qa[i].x*kb[j].x + qa[i].y*kb[j].y
                               + qa[i].z*kb[j].z + qa[i].w*kb[j].w;
        }
        // ---- scores 2 ----
        float sc2[4][4];
        #pragma unroll
        for (int i = 0; i < 4; i++)
            #pragma unroll
            for (int j = 0; j < 4; j++) sc2[i][j] = 0.f;
        #pragma unroll
        for (int kk = 0; kk < 64; kk += 4) {
            float4 qa[4], kb[4];
            #pragma unroll
            for (int i = 0; i < 4; i++) qa[i] = *(float4*)&Q2s[ty*4 + i][kk];
            #pragma unroll
            for (int j = 0; j < 4; j++) kb[j] = *(float4*)&K2s[tx + 16*j][kk];
            #pragma unroll
            for (int i = 0; i < 4; i++)
                #pragma unroll
                for (int j = 0; j < 4; j++)
                    sc2[i][j] += qa[i].x*kb[j].x + qa[i].y*kb[j].y
                               + qa[i].z*kb[j].z + qa[i].w*kb[j].w;
        }

        // scale + causal mask  (s = c0 + tx + 16*j)
        #pragma unroll
        for (int i = 0; i < 4; i++)
            #pragma unroll
            for (int j = 0; j < 4; j++) {
                sc1[i][j] *= 0.125f;
                sc2[i][j] *= 0.125f;
                if (diag) {
                    int t = t0 + ty*4 + i, s = c0 + tx + 16*j;
                    if (s > t) { sc1[i][j] = -1e30f; sc2[i][j] = -1e30f; }
                }
            }

        // ---- dual online softmax update ----
        #pragma unroll
        for (int i = 0; i < 4; i++) {
            float rm1 = fmaxf(fmaxf(sc1[i][0], sc1[i][1]), fmaxf(sc1[i][2], sc1[i][3]));
            float rm2 = fmaxf(fmaxf(sc2[i][0], sc2[i][1]), fmaxf(sc2[i][2], sc2[i][3]));
            #pragma unroll
            for (int m = 1; m < 16; m <<= 1) {
                rm1 = fmaxf(rm1, __shfl_xor_sync(0xffffffffu, rm1, m));
                rm2 = fmaxf(rm2, __shfl_xor_sync(0xffffffffu, rm2, m));
            }
            float mn1 = fmaxf(m1[i], rm1);
            float mn2 = fmaxf(m2[i], rm2);
            float f1 = __expf(m1[i] - mn1);
            float f2 = __expf(m2[i] - mn2);
            m1[i] = mn1; m2[i] = mn2;

            float rs1 = 0.f, rs2 = 0.f;
            #pragma unroll
            for (int j = 0; j < 4; j++) {
                float e1 = __expf(sc1[i][j] - mn1);
                float e2 = __expf(sc2[i][j] - mn2);
                P1s[ty*4 + i][tx + 16*j] = e1;
                P2s[ty*4 + i][tx + 16*j] = e2;
                rs1 += e1; rs2 += e2;
            }
            #pragma unroll
            for (int m = 1; m < 16; m <<= 1) {
                rs1 += __shfl_xor_sync(0xffffffffu, rs1, m);
                rs2 += __shfl_xor_sync(0xffffffffu, rs2, m);
            }
            l1[i] = l1[i] * f1 + rs1;
            l2[i] = l2[i] * f2 + rs2;
            #pragma unroll
            for (int j = 0; j < 4; j++) { o1[i][j] *= f1; o2[i][j] *= f2; }
        }
        __syncthreads();

        // ---- O += P @ V (both mats); P column kk is smem s-index, matching
        //      V row kk directly (the interleave permutes s consistently
        //      because P was stored at smem col = the s's smem row). ----
        #pragma unroll
        for (int kk = 0; kk < 64; kk += 4) {
            float4 vb[4];
            // V rows must follow the SAME interleaved permutation as P cols:
            // P smem col (tx' + 16*j') holds s-index c0 + tx' + 16*j', and
            // Vs row r holds s-index c0 + r, so P col c pairs with Vs row c. OK.
            #pragma unroll
            for (int l = 0; l < 4; l++) vb[l] = *(float4*)&Vs[kk + l][tx*4];
            float4 pa1[4], pa2[4];
            #pragma unroll
            for (int i = 0; i < 4; i++) {
                pa1[i] = *(float4*)&P1s[ty*4 + i][kk];
                pa2[i] = *(float4*)&P2s[ty*4 + i][kk];
            }
            #pragma unroll
            for (int i = 0; i < 4; i++) {
                o1[i][0] += pa1[i].x*vb[0].x + pa1[i].y*vb[1].x + pa1[i].z*vb[2].x + pa1[i].w*vb[3].x;
                o1[i][1] += pa1[i].x*vb[0].y + pa1[i].y*vb[1].y + pa1[i].z*vb[2].y + pa1[i].w*vb[3].y;
                o1[i][2] += pa1[i].x*vb[0].z + pa1[i].y*vb[1].z + pa1[i].z*vb[2].z + pa1[i].w*vb[3].z;
                o1[i][3] += pa1[i].x*vb[0].w + pa1[i].y*vb[1].w + pa1[i].z*vb[2].w + pa1[i].w*vb[3].w;
                o2[i][0] += pa2[i].x*vb[0].x + pa2[i].y*vb[1].x + pa2[i].z*vb[2].x + pa2[i].w*vb[3].x;
                o2[i][1] += pa2[i].x*vb[0].y + pa2[i].y*vb[1].y + pa2[i].z*vb[2].y + pa2[i].w*vb[3].y;
                o2[i][2] += pa2[i].x*vb[0].z + pa2[i].y*vb[1].z + pa2[i].z*vb[2].z + pa2[i].w*vb[3].z;
                o2[i][3] += pa2[i].x*vb[0].w + pa2[i].y*vb[1].w + pa2[i].z*vb[2].w + pa2[i].w*vb[3].w;
            }
        }
        __syncthreads();
    }

    // ---- epilogue: combine, per-head RMSNorm, store (d cols = tx*4..+3) ----
    float lam = lam_sh;
    #pragma unroll
    for (int i = 0; i < 4; i++) {
        float inv1 = 1.f / l1[i];
        float inv2 = lam / l2[i];
        float of[4];
        float ss = 0.f;
        #pragma unroll
        for (int j = 0; j < 4; j++) {
            of[j] = o1[i][j] * inv1 - o2[i][j] * inv2;
            ss += of[j] * of[j];
        }
        #pragma unroll
        for (int m = 1; m < 16; m <<= 1)
            ss += __shfl_xor_sync(0xffffffffu, ss, m);
        float rn = rsqrtf(ss * (1.f / 64.f) + 1e-6f) * 0.2f;
        float4 r;
        r.x = of[0] * rn; r.y = of[1] * rn; r.z = of[2] * rn; r.w = of[3] * rn;
        int t = t0 + ty*4 + i;
        *(float4*)(o + ((size_t)((b * TT + t) * HH + h)) * 64 + tx*4) = r;
    }
}

// ---------------- SwiGLU elementwise: a = silu(a) * b ----------------
__global__ void swiglu_ew_kernel(float* __restrict__ a, const float* __restrict__ b, int n)
{
    int i = blockIdx.x * blockDim.x + threadIdx.x;
    if (i < n) {
        float x = a[i];
        a[i] = (x / (1.f + expf(-x))) * b[i];
    }
}

// ---------------- launch ----------------
static inline void gemm(const float* A, const float* B, const float* add,
                        float* C, int M, int N, int K, float scale)
{
    dim3 grid(N / 128, M / 128);
    gemm_kernel<<<grid, 256>>>(A, B, add, C, M, N, K, scale);
}

extern "C" void kernel_launch(void* const* d_in, const int* in_sizes, int n_in,
                              void* d_out, int out_size)
{
    const float* x     = (const float*)d_in[0];
    const float* enc   = (const float*)d_in[1];
    const float* Wq_s  = (const float*)d_in[2];
    const float* Wk_s  = (const float*)d_in[3];
    const float* Wv_s  = (const float*)d_in[4];
    const float* Wo_s  = (const float*)d_in[5];
    const float* lq1_s = (const float*)d_in[6];
    const float* lk1_s = (const float*)d_in[7];
    const float* lq2_s = (const float*)d_in[8];
    const float* lk2_s = (const float*)d_in[9];
    const float* Wq_c  = (const float*)d_in[10];
    const float* Wk_c  = (const float*)d_in[11];
    const float* Wv_c  = (const float*)d_in[12];
    const float* Wo_c  = (const float*)d_in[13];
    const float* lq1_c = (const float*)d_in[14];
    const float* lk1_c = (const float*)d_in[15];
    const float* lq2_c = (const float*)d_in[16];
    const float* lk2_c = (const float*)d_in[17];
    const float* g_rms = (const float*)d_in[18];
    const float* W1    = (const float*)d_in[19];
    const float* W2    = (const float*)d_in[20];
    const float* W3    = (const float*)d_in[21];
    float* out = (float*)d_out;

    float *xn, *qb, *kb, *vb, *ob, *hb, *f1, *f2;
    cudaGetSymbolAddress((void**)&xn, buf_xn);
    cudaGetSymbolAddress((void**)&qb, buf_q);
    cudaGetSymbolAddress((void**)&kb, buf_k);
    cudaGetSymbolAddress((void**)&vb, buf_v);
    cudaGetSymbolAddress((void**)&ob, buf_o);
    cudaGetSymbolAddress((void**)&hb, buf_h);
    cudaGetSymbolAddress((void**)&f1, buf_f1);
    cudaGetSymbolAddress((void**)&f2, buf_f2);

    const int M = ROWS;
    const int attn_smem = 7 * 64 * ALD * (int)sizeof(float);  // ~119 KB
    cudaFuncSetAttribute(flash_diff_attn_kernel,
                         cudaFuncAttributeMaxDynamicSharedMemorySize, attn_smem);
    dim3 attn_grid(TT / 64, HH, BB);

    // 1) xn = rmsnorm(x, g_rms)
    rmsnorm_kernel<<<ROWS, 256>>>(x, g_rms, xn);

    // 2) self-attention projections
    gemm(xn, Wq_s, nullptr, qb, M, 2 * DD, DD, 1.f);
    gemm(xn, Wk_s, nullptr, kb, M, 2 * DD, DD, 1.f);
    gemm(xn, Wv_s, nullptr, vb, M, DD, DD, 1.f);

    // 3) causal diff attention
    flash_diff_attn_kernel<<<attn_grid, 256, attn_smem>>>(
        qb, kb, vb, lq1_s, lk1_s, lq2_s, lk2_s, ob, 1);

    // 4) h = o @ Wo_s + xn   (residual)
    gemm(ob, Wo_s, xn, hb, M, DD, DD, 1.f);

    // 5) cross-attention projections: q from h, k/v from encoder_output
    gemm(hb, Wq_c, nullptr, qb, M, 2 * DD, DD, 1.f);
    gemm(enc, Wk_c, nullptr, kb, M, 2 * DD, DD, 1.f);
    gemm(enc, Wv_c, nullptr, vb, M, DD, DD, 1.f);

    // 6) non-causal diff attention
    flash_diff_attn_kernel<<<attn_grid, 256, attn_smem>>>(
        qb, kb, vb, lq1_c, lk1_c, lq2_c, lk2_c, ob, 0);

    // 7) h = 2 * (o @ Wo_c)   (h = cross; h = h + h)
    gemm(ob, Wo_c, nullptr, hb, M, DD, DD, 2.f);

    // 8) xn = rmsnorm(h, g_rms)
    rmsnorm_kernel<<<ROWS, 256>>>(hb, g_rms, xn);

    // 9) SwiGLU MLP
    gemm(xn, W1, nullptr, f1, M, DFF, DD, 1.f);
    gemm(xn, W2, nullptr, f2, M, DFF, DD, 1.f);
    {
        int n = ROWS * DFF;
        swiglu_ew_kernel<<<(n + 255) / 256, 256>>>(f1, f2, n);
    }

    // 10) out = f1 @ W3 + h
    gemm(f1, W3, hb, out, M, DD, DFF, 1.f);
}

// round 13
// speedup vs baseline: 6.1122x; 1.1272x over previous
#include <cuda_runtime.h>
#include <cuda_bf16.h>
#include <math.h>
#include <stdint.h>

// Problem constants (fixed shapes from setup_inputs)
#define BB 4
#define TT 1024
#define SS 1024
#define DD 1024
#define HH 16
#define DFF 4096
#define ROWS (BB*TT)       // 4096

// ---------------- scratch buffers (static device allocations) ----------------
__device__ float buf_xn[ROWS * DD];
__device__ float buf_q [ROWS * 2*DD];
__device__ float buf_k [ROWS * 2*DD];
__device__ float buf_v [ROWS * DD];
__device__ float buf_o [ROWS * DD];
__device__ float buf_h [ROWS * DD];
__device__ float buf_f1[ROWS * DFF];
__device__ float buf_f2[ROWS * DFF];

// bf16 split buffers
__device__ __align__(16) __nv_bfloat16 buf_ah[ROWS * DFF];   // activation hi
__device__ __align__(16) __nv_bfloat16 buf_al[ROWS * DFF];   // activation lo
#define WTOT 25165824
__device__ __align__(16) __nv_bfloat16 buf_wh[WTOT];         // weights hi, [N,K]
__device__ __align__(16) __nv_bfloat16 buf_wl[WTOT];         // weights lo
// weight offsets (elements)
#define OFF_QS 0
#define OFF_KS 2097152
#define OFF_VS 4194304
#define OFF_OS 5242880
#define OFF_QC 6291456
#define OFF_KC 8388608
#define OFF_VC 10485760
#define OFF_OC 11534336
#define OFF_W1 12582912
#define OFF_W2 16777216
#define OFF_W3 20971520

// ================= PTX helpers (base-target only: ldmatrix/mma.sync/cp.async) =====
static __device__ __forceinline__ uint32_t smem_u32(const void* p) {
    uint32_t a;
    asm("{ .reg .u64 t; cvta.to.shared.u64 t, %1; cvt.u32.u64 %0, t; }" : "=r"(a) : "l"(p));
    return a;
}
static __device__ __forceinline__ void cp16(uint32_t dst, const void* src) {
    asm volatile("cp.async.cg.shared.global [%0], [%1], 16;" :: "r"(dst), "l"(src));
}
static __device__ __forceinline__ void cp_commit() {
    asm volatile("cp.async.commit_group;" ::: "memory");
}
template <int N>
static __device__ __forceinline__ void cp_wait() {
    asm volatile("cp.async.wait_group %0;" :: "n"(N) : "memory");
}
static __device__ __forceinline__ void ldsm4(uint32_t* r, uint32_t a) {
    asm volatile("ldmatrix.sync.aligned.m8n8.x4.shared.b16 {%0,%1,%2,%3}, [%4];"
        : "=r"(r[0]), "=r"(r[1]), "=r"(r[2]), "=r"(r[3]) : "r"(a));
}
static __device__ __forceinline__ void mma16816(float* c, const uint32_t* a, const uint32_t* b) {
    asm volatile(
        "mma.sync.aligned.m16n8k16.row.col.f32.bf16.bf16.f32 "
        "{%0,%1,%2,%3}, {%4,%5,%6,%7}, {%8,%9}, {%0,%1,%2,%3};"
        : "+f"(c[0]), "+f"(c[1]), "+f"(c[2]), "+f"(c[3])
        : "r"(a[0]), "r"(a[1]), "r"(a[2]), "r"(a[3]), "r"(b[0]), "r"(b[1]));
}

// ================= mma.sync GEMM =================
// C[M,N] = scale * ((Ah+Al) @ (Bh+Bl)^T) [+ add]   (drops Al*Bl)
// A: [M,K] bf16 K-major, B: [N,K] bf16 K-major. M%128==0, N%128==0, K%32==0.
#define GBM 128
#define GBN 128
#define GBK 32
#define LDT 40                      // smem row stride in bf16 (80 B; conflict-free ldmatrix)
#define STG_MAT (128*LDT*2)         // 10240 B per matrix tile
#define STG (4*STG_MAT)             // 40960 B per stage (Ah,Al,Bh,Bl)
#define GS_SMEM (2*STG)             // 81920 B double-buffered

__global__ __launch_bounds__(256, 1)
void mma_gemm_kernel(const __nv_bfloat16* __restrict__ Ah, const __nv_bfloat16* __restrict__ Al,
                     const __nv_bfloat16* __restrict__ Bh, const __nv_bfloat16* __restrict__ Bl,
                     const float* __restrict__ add, float* __restrict__ C,
                     int M, int N, int K, float scale)
{
    extern __shared__ char sm[];
    int tid = threadIdx.x;
    int wid = tid >> 5, lane = tid & 31;
    int m0 = blockIdx.y * GBM, n0 = blockIdx.x * GBN;
    int wm = (wid >> 2) * 64;       // warp m offset within block (0/64)
    int wn = (wid & 3) * 32;        // warp n offset within block (0/32/64/96)

    uint32_t sbase = smem_u32(sm);
    const char* pAh = (const char*)(Ah + (size_t)m0 * K);
    const char* pAl = (const char*)(Al + (size_t)m0 * K);
    const char* pBh = (const char*)(Bh + (size_t)n0 * K);
    const char* pBl = (const char*)(Bl + (size_t)n0 * K);
    size_t rowB = (size_t)K * 2;    // gmem row stride in bytes

    float acc[4][4][4];
    #pragma unroll
    for (int a = 0; a < 4; a++)
        #pragma unroll
        for (int b = 0; b < 4; b++)
            #pragma unroll
            for (int c = 0; c < 4; c++) acc[a][b][c] = 0.f;

    int nch = K / GBK;

    // ---- prefetch stage 0 ----
    {
        uint32_t sb = sbase;
        #pragma unroll
        for (int u = tid; u < 512; u += 256) {
            int r = u >> 2; int c = (u & 3) << 4;            // byte col 0,16,32,48
            size_t go = (size_t)r * rowB + c;
            uint32_t so = (uint32_t)(r * (LDT*2) + c);
            cp16(sb + 0*STG_MAT + so, pAh + go);
            cp16(sb + 1*STG_MAT + so, pAl + go);
            cp16(sb + 2*STG_MAT + so, pBh + go);
            cp16(sb + 3*STG_MAT + so, pBl + go);
        }
        cp_commit();
    }

    for (int ch = 0; ch < nch; ch++) {
        // issue next stage
        if (ch + 1 < nch) {
            uint32_t sb = sbase + ((ch + 1) & 1) * STG;
            int kc = (ch + 1) * GBK * 2;                    // byte offset in K
            #pragma unroll
            for (int u = tid; u < 512; u += 256) {
                int r = u >> 2; int c = (u & 3) << 4;
                size_t go = (size_t)r * rowB + kc + c;
                uint32_t so = (uint32_t)(r * (LDT*2) + c);
                cp16(sb + 0*STG_MAT + so, pAh + go);
                cp16(sb + 1*STG_MAT + so, pAl + go);
                cp16(sb + 2*STG_MAT + so, pBh + go);
                cp16(sb + 3*STG_MAT + so, pBl + go);
            }
            cp_commit();
            cp_wait<1>();
        } else {
            cp_wait<0>();
        }
        __syncthreads();

        uint32_t sb = sbase + (ch & 1) * STG;
        uint32_t aHb = sb, aLb = sb + STG_MAT, bHb = sb + 2*STG_MAT, bLb = sb + 3*STG_MAT;

        #pragma unroll
        for (int kk = 0; kk < 2; kk++) {                    // two k16 halves of GBK=32
            int kb = kk * 32;                                // byte offset: 16 bf16
            uint32_t aH[4][4], aL[4][4], bH[4][2], bL[4][2];

            // A fragments: 4 m16 tiles, canonical x4
            {
                int arow = wm + (lane & 15);
                int ahalf = (lane >> 4) << 4;               // 0 or 16 bytes (k half)
                #pragma unroll
                for (int mt = 0; mt < 4; mt++) {
                    uint32_t ad = (uint32_t)((arow + mt*16) * (LDT*2) + kb + ahalf);
                    ldsm4(aH[mt], aHb + ad);
                    ldsm4(aL[mt], aLb + ad);
                }
            }
            // B fragments: x4 covers two n8 tiles
            {
                int brow = wn + (lane & 7) + ((lane >> 4) << 3);
                int bhalf = ((lane >> 3) & 1) << 4;
                uint32_t bd0 = (uint32_t)(brow * (LDT*2) + kb + bhalf);
                uint32_t bd1 = (uint32_t)((brow + 16) * (LDT*2) + kb + bhalf);
                uint32_t t[4];
                ldsm4(t, bHb + bd0); bH[0][0]=t[0]; bH[0][1]=t[1]; bH[1][0]=t[2]; bH[1][1]=t[3];
                ldsm4(t, bHb + bd1); bH[2][0]=t[0]; bH[2][1]=t[1]; bH[3][0]=t[2]; bH[3][1]=t[3];
                ldsm4(t, bLb + bd0); bL[0][0]=t[0]; bL[0][1]=t[1]; bL[1][0]=t[2]; bL[1][1]=t[3];
                ldsm4(t, bLb + bd1); bL[2][0]=t[0]; bL[2][1]=t[1]; bL[3][0]=t[2]; bL[3][1]=t[3];
            }

            #pragma unroll
            for (int mt = 0; mt < 4; mt++)
                #pragma unroll
                for (int nt = 0; nt < 4; nt++) {
                    mma16816(acc[mt][nt], aH[mt], bH[nt]);
                    mma16816(acc[mt][nt], aH[mt], bL[nt]);
                    mma16816(acc[mt][nt], aL[mt], bH[nt]);
                }
        }
        __syncthreads();
    }

    // ---- epilogue: canonical m16n8 C fragment mapping ----
    #pragma unroll
    for (int mt = 0; mt < 4; mt++) {
        int row = m0 + wm + mt*16 + (lane >> 2);
        #pragma unroll
        for (int nt = 0; nt < 4; nt++) {
            int col = n0 + wn + nt*8 + (lane & 3)*2;
            size_t i0 = (size_t)row * N + col;
            size_t i1 = i0 + (size_t)8 * N;
            float2 v0, v1;
            v0.x = acc[mt][nt][0] * scale; v0.y = acc[mt][nt][1] * scale;
            v1.x = acc[mt][nt][2] * scale; v1.y = acc[mt][nt][3] * scale;
            if (add) {
                float2 a0 = *(const float2*)(add + i0);
                float2 a1 = *(const float2*)(add + i1);
                v0.x += a0.x; v0.y += a0.y; v1.x += a1.x; v1.y += a1.y;
            }
            *(float2*)(C + i0) = v0;
            *(float2*)(C + i1) = v1;
        }
    }
}

// ================= conversion kernels =================
__global__ void split_kernel(const float* __restrict__ s, __nv_bfloat16* __restrict__ h,
                             __nv_bfloat16* __restrict__ l, int n)
{
    int i = (blockIdx.x * 256 + threadIdx.x) * 4;
    if (i < n) {
        float4 v = *(const float4*)(s + i);
        float a[4] = {v.x, v.y, v.z, v.w};
        #pragma unroll
        for (int j = 0; j < 4; j++) {
            __nv_bfloat16 hb = __float2bfloat16(a[j]);
            h[i + j] = hb;
            l[i + j] = __float2bfloat16(a[j] - __bfloat162float(hb));
        }
    }
}

// fp32 src [K,N] -> bf16 hi/lo [N,K] (transposed)
__global__ void split_transpose_kernel(const float* __restrict__ src,
                                       __nv_bfloat16* __restrict__ dh,
                                       __nv_bfloat16* __restrict__ dl, int K, int N)
{
    __shared__ float tile[32][33];
    int n0 = blockIdx.x * 32, k0 = blockIdx.y * 32;
    int tx = threadIdx.x, ty = threadIdx.y;   // 32 x 8
    #pragma unroll
    for (int i = 0; i < 32; i += 8)
        tile[ty + i][tx] = src[(size_t)(k0 + ty + i) * N + n0 + tx];
    __syncthreads();
    #pragma unroll
    for (int i = 0; i < 32; i += 8) {
        float v = tile[tx][ty + i];
        __nv_bfloat16 hb = __float2bfloat16(v);
        size_t idx = (size_t)(n0 + ty + i) * K + k0 + tx;
        dh[idx] = hb;
        dl[idx] = __float2bfloat16(v - __bfloat162float(hb));
    }
}

// ---------------- RMSNorm: one block per row ----------------
__global__ void rmsnorm_kernel(const float* __restrict__ x,
                               const float* __restrict__ g,
                               float* __restrict__ out)
{
    int row = blockIdx.x;
    const float* xr = x + (size_t)row * DD;
    float* orow = out + (size_t)row * DD;

    float s = 0.f;
    for (int i = threadIdx.x * 4; i < DD; i += blockDim.x * 4) {
        float4 v = *(const float4*)(xr + i);
        s += v.x*v.x + v.y*v.y + v.z*v.z + v.w*v.w;
    }
    __shared__ float red[256];
    red[threadIdx.x] = s;
    __syncthreads();
    for (int st = 128; st > 0; st >>= 1) {
        if (threadIdx.x < st) red[threadIdx.x] += red[threadIdx.x + st];
        __syncthreads();
    }
    float inv = rsqrtf(red[0] * (1.f / DD) + 1e-6f);

    for (int i = threadIdx.x * 4; i < DD; i += blockDim.x * 4) {
        float4 v = *(const float4*)(xr + i);
        float4 gv = *(const float4*)(g + i);
        float4 r;
        r.x = v.x * inv * gv.x;
        r.y = v.y * inv * gv.y;
        r.z = v.z * inv * gv.z;
        r.w = v.w * inv * gv.w;
        *(float4*)(orow + i) = r;
    }
}

// ---------------- Flash-tiled differential attention ----------------
#define APAD 4
#define ALD (64 + APAD)

__global__ __launch_bounds__(256)
void flash_diff_attn_kernel(const float* __restrict__ q, const float* __restrict__ k,
                            const float* __restrict__ v,
                            const float* __restrict__ lq1, const float* __restrict__ lk1,
                            const float* __restrict__ lq2, const float* __restrict__ lk2,
                            float* __restrict__ o, int causal)
{
    extern __shared__ float smem[];
    float (*Q1s)[ALD] = (float(*)[ALD])(smem);
    float (*Q2s)[ALD] = (float(*)[ALD])(smem + 64*ALD);
    float (*K1s)[ALD] = (float(*)[ALD])(smem + 2*64*ALD);
    float (*K2s)[ALD] = (float(*)[ALD])(smem + 3*64*ALD);
    float (*Vs )[ALD] = (float(*)[ALD])(smem + 4*64*ALD);
    float (*P1s)[ALD] = (float(*)[ALD])(smem + 5*64*ALD);
    float (*P2s)[ALD] = (float(*)[ALD])(smem + 6*64*ALD);
    __shared__ float lam_sh;

    int qt = blockIdx.x, h = blockIdx.y, b = blockIdx.z;
    int t0 = qt * 64;
    int tid = threadIdx.x;
    int tx = tid & 15;
    int ty = tid >> 4;

    if (tid == 0) {
        float s1 = 0.f, s2 = 0.f;
        #pragma unroll 8
        for (int d = 0; d < 64; d++) {
            s1 += lq1[h * 64 + d] * lk1[h * 64 + d];
            s2 += lq2[h * 64 + d] * lk2[h * 64 + d];
        }
        lam_sh = expf(s1) - expf(s2) + 0.8f;
    }

    for (int i = tid; i < 64 * 16; i += 256) {
        int r = i >> 4, dg = (i & 15) * 4;
        const float* qrow = q + ((size_t)((b * TT + t0 + r) * HH + h)) * 128;
        *(float4*)&Q1s[r][dg] = *(const float4*)(qrow + dg);
        *(float4*)&Q2s[r][dg] = *(const float4*)(qrow + 64 + dg);
    }

    float m1[4], m2[4], l1[4], l2[4];
    float o1[4][4], o2[4][4];
    #pragma unroll
    for (int i = 0; i < 4; i++) {
        m1[i] = -1e30f; m2[i] = -1e30f; l1[i] = 0.f; l2[i] = 0.f;
        #pragma unroll
        for (int j = 0; j < 4; j++) { o1[i][j] = 0.f; o2[i][j] = 0.f; }
    }

    int nChunk = causal ? (qt + 1) : (SS / 64);

    for (int ch = 0; ch < nChunk; ch++) {
        int c0 = ch * 64;
        for (int i = tid; i < 64 * 16; i += 256) {
            int r = i >> 4, dg = (i & 15) * 4;
            const float* krow = k + ((size_t)((b * SS + c0 + r) * HH + h)) * 128;
            *(float4*)&K1s[r][dg] = *(const float4*)(krow + dg);
            *(float4*)&K2s[r][dg] = *(const float4*)(krow + 64 + dg);
            const float* vrow = v + ((size_t)((b * SS + c0 + r) * HH + h)) * 64;
            *(float4*)&Vs[r][dg] = *(const float4*)(vrow + dg);
        }
        __syncthreads();

        bool diag = causal && (ch == nChunk - 1);

        float sc1[4][4];
        #pragma unroll
        for (int i = 0; i < 4; i++)
            #pragma unroll
            for (int j = 0; j < 4; j++) sc1[i][j] = 0.f;
        #pragma unroll
        for (int kk = 0; kk < 64; kk += 4) {
            float4 qa[4], kb[4];
            #pragma unroll
            for (int i = 0; i < 4; i++) qa[i] = *(float4*)&Q1s[ty*4 + i][kk];
            #pragma unroll
            for (int j = 0; j < 4; j++) kb[j] = *(float4*)&K1s[tx + 16*j][kk];
            #pragma unroll
            for (int i = 0; i < 4; i++)
                #pragma unroll
                for (int j = 0; j < 4; j++)
                    sc1[i][j] += qa[i].x*kb[j].x + qa[i].y*kb[j].y
                               + qa[i].z*kb[j].z + qa[i].w*kb[j].w;
        }
        float sc2[4][4];
        #pragma unroll
        for (int i = 0; i < 4; i++)
            #pragma unroll
            for (int j = 0; j < 4; j++) sc2[i][j] = 0.f;
        #pragma unroll
        for (int kk = 0; kk < 64; kk += 4) {
            float4 qa[4], kb[4];
            #pragma unroll
            for (int i = 0; i < 4; i++) qa[i] = *(float4*)&Q2s[ty*4 + i][kk];
            #pragma unroll
            for (int j = 0; j < 4; j++) kb[j] = *(float4*)&K2s[tx + 16*j][kk];
            #pragma unroll
            for (int i = 0; i < 4; i++)
                #pragma unroll
                for (int j = 0; j < 4; j++)
                    sc2[i][j] += qa[i].x*kb[j].x + qa[i].y*kb[j].y
                               + qa[i].z*kb[j].z + qa[i].w*kb[j].w;
        }

        #pragma unroll
        for (int i = 0; i < 4; i++)
            #pragma unroll
            for (int j = 0; j < 4; j++) {
                sc1[i][j] *= 0.125f;
                sc2[i][j] *= 0.125f;
                if (diag) {
                    int t = t0 + ty*4 + i, s = c0 + tx + 16*j;
                    if (s > t) { sc1[i][j] = -1e30f; sc2[i][j] = -1e30f; }
                }
            }

        #pragma unroll
        for (int i = 0; i < 4; i++) {
            float rm1 = fmaxf(fmaxf(sc1[i][0], sc1[i][1]), fmaxf(sc1[i][2], sc1[i][3]));
            float rm2 = fmaxf(fmaxf(sc2[i][0], sc2[i][1]), fmaxf(sc2[i][2], sc2[i][3]));
            #pragma unroll
            for (int m = 1; m < 16; m <<= 1) {
                rm1 = fmaxf(rm1, __shfl_xor_sync(0xffffffffu, rm1, m));
                rm2 = fmaxf(rm2, __shfl_xor_sync(0xffffffffu, rm2, m));
            }
            float mn1 = fmaxf(m1[i], rm1);
            float mn2 = fmaxf(m2[i], rm2);
            float f1 = __expf(m1[i] - mn1);
            float f2 = __expf(m2[i] - mn2);
            m1[i] = mn1; m2[i] = mn2;

            float rs1 = 0.f, rs2 = 0.f;
            #pragma unroll
            for (int j = 0; j < 4; j++) {
                float e1 = __expf(sc1[i][j] - mn1);
                float e2 = __expf(sc2[i][j] - mn2);
                P1s[ty*4 + i][tx + 16*j] = e1;
                P2s[ty*4 + i][tx + 16*j] = e2;
                rs1 += e1; rs2 += e2;
            }
            #pragma unroll
            for (int m = 1; m < 16; m <<= 1) {
                rs1 += __shfl_xor_sync(0xffffffffu, rs1, m);
                rs2 += __shfl_xor_sync(0xffffffffu, rs2, m);
            }
            l1[i] = l1[i] * f1 + rs1;
            l2[i] = l2[i] * f2 + rs2;
            #pragma unroll
            for (int j = 0; j < 4; j++) { o1[i][j] *= f1; o2[i][j] *= f2; }
        }
        __syncthreads();

        #pragma unroll
        for (int kk = 0; kk < 64; kk += 4) {
            float4 vb[4];
            #pragma unroll
            for (int l = 0; l < 4; l++) vb[l] = *(float4*)&Vs[kk + l][tx*4];
            float4 pa1[4], pa2[4];
            #pragma unroll
            for (int i = 0; i < 4; i++) {
                pa1[i] = *(float4*)&P1s[ty*4 + i][kk];
                pa2[i] = *(float4*)&P2s[ty*4 + i][kk];
            }
            #pragma unroll
            for (int i = 0; i < 4; i++) {
                o1[i][0] += pa1[i].x*vb[0].x + pa1[i].y*vb[1].x + pa1[i].z*vb[2].x + pa1[i].w*vb[3].x;
                o1[i][1] += pa1[i].x*vb[0].y + pa1[i].y*vb[1].y + pa1[i].z*vb[2].y + pa1[i].w*vb[3].y;
                o1[i][2] += pa1[i].x*vb[0].z + pa1[i].y*vb[1].z + pa1[i].z*vb[2].z + pa1[i].w*vb[3].z;
                o1[i][3] += pa1[i].x*vb[0].w + pa1[i].y*vb[1].w + pa1[i].z*vb[2].w + pa1[i].w*vb[3].w;
                o2[i][0] += pa2[i].x*vb[0].x + pa2[i].y*vb[1].x + pa2[i].z*vb[2].x + pa2[i].w*vb[3].x;
                o2[i][1] += pa2[i].x*vb[0].y + pa2[i].y*vb[1].y + pa2[i].z*vb[2].y + pa2[i].w*vb[3].y;
                o2[i][2] += pa2[i].x*vb[0].z + pa2[i].y*vb[1].z + pa2[i].z*vb[2].z + pa2[i].w*vb[3].z;
                o2[i][3] += pa2[i].x*vb[0].w + pa2[i].y*vb[1].w + pa2[i].z*vb[2].w + pa2[i].w*vb[3].w;
            }
        }
        __syncthreads();
    }

    float lam = lam_sh;
    #pragma unroll
    for (int i = 0; i < 4; i++) {
        float inv1 = 1.f / l1[i];
        float inv2 = lam / l2[i];
        float of[4];
        float ss = 0.f;
        #pragma unroll
        for (int j = 0; j < 4; j++) {
            of[j] = o1[i][j] * inv1 - o2[i][j] * inv2;
            ss += of[j] * of[j];
        }
        #pragma unroll
        for (int m = 1; m < 16; m <<= 1)
            ss += __shfl_xor_sync(0xffffffffu, ss, m);
        float rn = rsqrtf(ss * (1.f / 64.f) + 1e-6f) * 0.2f;
        float4 r;
        r.x = of[0] * rn; r.y = of[1] * rn; r.z = of[2] * rn; r.w = of[3] * rn;
        int t = t0 + ty*4 + i;
        *(float4*)(o + ((size_t)((b * TT + t) * HH + h)) * 64 + tx*4) = r;
    }
}

// ---------------- SwiGLU elementwise: a = silu(a) * b ----------------
__global__ void swiglu_ew_kernel(float* __restrict__ a, const float* __restrict__ b, int n)
{
    int i = blockIdx.x * blockDim.x + threadIdx.x;
    if (i < n) {
        float x = a[i];
        a[i] = (x / (1.f + expf(-x))) * b[i];
    }
}

// ---------------- launch helpers ----------------
static inline void tcgemm(const __nv_bfloat16* Ah, const __nv_bfloat16* Al,
                          const __nv_bfloat16* Bh, const __nv_bfloat16* Bl,
                          const float* add, float* C, int M, int N, int K, float scale)
{
    dim3 grid(N / GBN, M / GBM);
    mma_gemm_kernel<<<grid, 256, GS_SMEM>>>(Ah, Al, Bh, Bl, add, C, M, N, K, scale);
}

static inline void splitA(const float* s, __nv_bfloat16* h, __nv_bfloat16* l, int n)
{
    split_kernel<<<n / 1024, 256>>>(s, h, l, n);
}

extern "C" void kernel_launch(void* const* d_in, const int* in_sizes, int n_in,
                              void* d_out, int out_size)
{
    const float* x     = (const float*)d_in[0];
    const float* enc   = (const float*)d_in[1];
    const float* Wq_s  = (const float*)d_in[2];
    const float* Wk_s  = (const float*)d_in[3];
    const float* Wv_s  = (const float*)d_in[4];
    const float* Wo_s  = (const float*)d_in[5];
    const float* lq1_s = (const float*)d_in[6];
    const float* lk1_s = (const float*)d_in[7];
    const float* lq2_s = (const float*)d_in[8];
    const float* lk2_s = (const float*)d_in[9];
    const float* Wq_c  = (const float*)d_in[10];
    const float* Wk_c  = (const float*)d_in[11];
    const float* Wv_c  = (const float*)d_in[12];
    const float* Wo_c  = (const float*)d_in[13];
    const float* lq1_c = (const float*)d_in[14];
    const float* lk1_c = (const float*)d_in[15];
    const float* lq2_c = (const float*)d_in[16];
    const float* lk2_c = (const float*)d_in[17];
    const float* g_rms = (const float*)d_in[18];
    const float* W1    = (const float*)d_in[19];
    const float* W2    = (const float*)d_in[20];
    const float* W3    = (const float*)d_in[21];
    float* out = (float*)d_out;

    float *xn, *qb, *kb, *vb, *ob, *hb, *f1, *f2;
    __nv_bfloat16 *ah, *al, *wh, *wl;
    cudaGetSymbolAddress((void**)&xn, buf_xn);
    cudaGetSymbolAddress((void**)&qb, buf_q);
    cudaGetSymbolAddress((void**)&kb, buf_k);
    cudaGetSymbolAddress((void**)&vb, buf_v);
    cudaGetSymbolAddress((void**)&ob, buf_o);
    cudaGetSymbolAddress((void**)&hb, buf_h);
    cudaGetSymbolAddress((void**)&f1, buf_f1);
    cudaGetSymbolAddress((void**)&f2, buf_f2);
    cudaGetSymbolAddress((void**)&ah, buf_ah);
    cudaGetSymbolAddress((void**)&al, buf_al);
    cudaGetSymbolAddress((void**)&wh, buf_wh);
    cudaGetSymbolAddress((void**)&wl, buf_wl);

    cudaFuncSetAttribute(mma_gemm_kernel,
                         cudaFuncAttributeMaxDynamicSharedMemorySize, GS_SMEM);
    const int attn_smem = 7 * 64 * ALD * (int)sizeof(float);
    cudaFuncSetAttribute(flash_diff_attn_kernel,
                         cudaFuncAttributeMaxDynamicSharedMemorySize, attn_smem);

    const int M = ROWS;
    dim3 attn_grid(TT / 64, HH, BB);
    dim3 tb(32, 8);

    // ---- weight conversions: fp32 [K,N] -> bf16 hi/lo [N,K] ----
    split_transpose_kernel<<<dim3(2048/32, 1024/32), tb>>>(Wq_s, wh + OFF_QS, wl + OFF_QS, 1024, 2048);
    split_transpose_kernel<<<dim3(2048/32, 1024/32), tb>>>(Wk_s, wh + OFF_KS, wl + OFF_KS, 1024, 2048);
    split_transpose_kernel<<<dim3(1024/32, 1024/32), tb>>>(Wv_s, wh + OFF_VS, wl + OFF_VS, 1024, 1024);
    split_transpose_kernel<<<dim3(1024/32, 1024/32), tb>>>(Wo_s, wh + OFF_OS, wl + OFF_OS, 1024, 1024);
    split_transpose_kernel<<<dim3(2048/32, 1024/32), tb>>>(Wq_c, wh + OFF_QC, wl + OFF_QC, 1024, 2048);
    split_transpose_kernel<<<dim3(2048/32, 1024/32), tb>>>(Wk_c, wh + OFF_KC, wl + OFF_KC, 1024, 2048);
    split_transpose_kernel<<<dim3(1024/32, 1024/32), tb>>>(Wv_c, wh + OFF_VC, wl + OFF_VC, 1024, 1024);
    split_transpose_kernel<<<dim3(1024/32, 1024/32), tb>>>(Wo_c, wh + OFF_OC, wl + OFF_OC, 1024, 1024);
    split_transpose_kernel<<<dim3(4096/32, 1024/32), tb>>>(W1,   wh + OFF_W1, wl + OFF_W1, 1024, 4096);
    split_transpose_kernel<<<dim3(4096/32, 1024/32), tb>>>(W2,   wh + OFF_W2, wl + OFF_W2, 1024, 4096);
    split_transpose_kernel<<<dim3(1024/32, 4096/32), tb>>>(W3,   wh + OFF_W3, wl + OFF_W3, 4096, 1024);

    // 1) xn = rmsnorm(x)
    rmsnorm_kernel<<<ROWS, 256>>>(x, g_rms, xn);
    splitA(xn, ah, al, M * DD);

    // 2) self-attention projections
    tcgemm(ah, al, wh + OFF_QS, wl + OFF_QS, nullptr, qb, M, 2*DD, DD, 1.f);
    tcgemm(ah, al, wh + OFF_KS, wl + OFF_KS, nullptr, kb, M, 2*DD, DD, 1.f);
    tcgemm(ah, al, wh + OFF_VS, wl + OFF_VS, nullptr, vb, M, DD, DD, 1.f);

    // 3) causal diff attention
    flash_diff_attn_kernel<<<attn_grid, 256, attn_smem>>>(
        qb, kb, vb, lq1_s, lk1_s, lq2_s, lk2_s, ob, 1);

    // 4) h = o @ Wo_s + xn
    splitA(ob, ah, al, M * DD);
    tcgemm(ah, al, wh + OFF_OS, wl + OFF_OS, xn, hb, M, DD, DD, 1.f);

    // 5) cross projections
    splitA(hb, ah, al, M * DD);
    tcgemm(ah, al, wh + OFF_QC, wl + OFF_QC, nullptr, qb, M, 2*DD, DD, 1.f);
    splitA(enc, ah, al, M * DD);
    tcgemm(ah, al, wh + OFF_KC, wl + OFF_KC, nullptr, kb, M, 2*DD, DD, 1.f);
    tcgemm(ah, al, wh + OFF_VC, wl + OFF_VC, nullptr, vb, M, DD, DD, 1.f);

    // 6) non-causal diff attention
    flash_diff_attn_kernel<<<attn_grid, 256, attn_smem>>>(
        qb, kb, vb, lq1_c, lk1_c, lq2_c, lk2_c, ob, 0);

    // 7) h = 2 * (o @ Wo_c)
    splitA(ob, ah, al, M * DD);
    tcgemm(ah, al, wh + OFF_OC, wl + OFF_OC, nullptr, hb, M, DD, DD, 2.f);

    // 8) xn = rmsnorm(h)
    rmsnorm_kernel<<<ROWS, 256>>>(hb, g_rms, xn);
    splitA(xn, ah, al, M * DD);

    // 9) SwiGLU MLP
    tcgemm(ah, al, wh + OFF_W1, wl + OFF_W1, nullptr, f1, M, DFF, DD, 1.f);
    tcgemm(ah, al, wh + OFF_W2, wl + OFF_W2, nullptr, f2, M, DFF, DD, 1.f);
    {
        int n = ROWS * DFF;
        swiglu_ew_kernel<<<(n + 255) / 256, 256>>>(f1, f2, n);
    }

    // 10) out = f1 @ W3 + h
    splitA(f1, ah, al, M * DFF);
    tcgemm(ah, al, wh + OFF_W3, wl + OFF_W3, hb, out, M, DD, DFF, 1.f);
}